// round 13
// baseline (speedup 1.0000x reference)
#include <cuda_runtime.h>
#include <cuda_bf16.h>
#include <cstdint>

// Problem constants
#define NN 2048
#define BB 256
#define TT 256
#define CC 2
#define SLOPE 8.0f

// GEMM tiling: CTA 64x64, k-chunk 64, 512 threads (16 warps = 4 wg x (2x2))
// Each wg owns k16 slice wg of every chunk: private fill + private barrier.
#define BM 64
#define BN 64
#define BK 64
#define NIT (NN / BK)   // 32
#define THREADS 512

#define WG_TILE_B 2048            // 64 rows x 32 B (one wg's k16 slice of a tile)
#define WG_B (4 * WG_TILE_B)      // per-wg slice of a stage: Ah,Al,Bh,Bl = 8KB
#define STAGE_B (4 * WG_B)        // 32768 B
#define NSTAGE 4
#define SMEM_PAR 0                // 7 x 64 floats = 1792 B
#define SMEM_STAGE 2048
#define SMEM_TOTAL (SMEM_STAGE + NSTAGE * STAGE_B)  // 133120 B

// Scratch, double-buffered in t-parity (allocation-free rule)
__device__ __align__(256) __nv_bfloat16 g_a_hi[2 * BB * NN];
__device__ __align__(256) __nv_bfloat16 g_a_lo[2 * BB * NN];
__device__ __align__(256) __nv_bfloat16 g_w_hi[NN * NN];
__device__ __align__(256) __nv_bfloat16 g_w_lo[NN * NN];

// ---------------------------------------------------------------------------
__device__ __forceinline__ uint32_t s2u(const void* p) {
    uint32_t a;
    asm("{ .reg .u64 t; cvta.to.shared.u64 t, %1; cvt.u32.u64 %0, t; }"
        : "=r"(a) : "l"(p));
    return a;
}

__device__ __forceinline__ void cp16(uint32_t dst, const void* src) {
    asm volatile("cp.async.cg.shared.global [%0], [%1], 16;\n"
                 :: "r"(dst), "l"(src));
}
#define CP_COMMIT() asm volatile("cp.async.commit_group;\n" ::: "memory")
#define CP_WAIT(n)  asm volatile("cp.async.wait_group %0;\n" :: "n"(n) : "memory")
#define WG_BAR(id)  asm volatile("bar.sync %0, 128;" :: "r"(id) : "memory")

__device__ __forceinline__ void ldsm4(uint32_t* r, uint32_t addr) {
    asm volatile("ldmatrix.sync.aligned.m8n8.x4.shared.b16 {%0,%1,%2,%3}, [%4];"
                 : "=r"(r[0]), "=r"(r[1]), "=r"(r[2]), "=r"(r[3]) : "r"(addr));
}

__device__ __forceinline__ void mma16816(float* c, const uint32_t* a,
                                         uint32_t b0, uint32_t b1) {
    asm volatile("mma.sync.aligned.m16n8k16.row.col.f32.bf16.bf16.f32 "
                 "{%0,%1,%2,%3}, {%4,%5,%6,%7}, {%8,%9}, {%0,%1,%2,%3};"
                 : "+f"(c[0]), "+f"(c[1]), "+f"(c[2]), "+f"(c[3])
                 : "r"(a[0]), "r"(a[1]), "r"(a[2]), "r"(a[3]),
                   "r"(b0), "r"(b1));
}

// ---------------------------------------------------------------------------
__global__ void zero_kernel(float* __restrict__ out, int n) {
    int i = blockIdx.x * blockDim.x + threadIdx.x;
    if (i < n) out[i] = 0.0f;
}

// W fp32 -> hi/lo bf16 (once per launch)
__global__ void wconv_kernel(const float* __restrict__ W) {
    int i = blockIdx.x * blockDim.x + threadIdx.x;
    if (i < NN * NN) {
        float w = W[i];
        __nv_bfloat16 h = __float2bfloat16_rn(w);
        g_w_hi[i] = h;
        g_w_lo[i] = __float2bfloat16_rn(w - __bfloat162float(h));
    }
}

// s'(0) = state0 + mask * ext(t=0), split hi/lo, into parity-0 buffer
__global__ void prep0_kernel(const float* __restrict__ state0,
                             const float* __restrict__ inputs,
                             const float* __restrict__ mask,
                             const float* __restrict__ enc) {
    int i = blockIdx.x * blockDim.x + threadIdx.x;
    int b = i >> 11;
    int n = i & (NN - 1);
    float x0 = inputs[b * TT];
    float x1 = inputs[(BB + b) * TT];
    float sp = state0[i] + mask[n] * (x0 * enc[n] + x1 * enc[NN + n]);
    __nv_bfloat16 h = __float2bfloat16_rn(sp);
    g_a_hi[i] = h;
    g_a_lo[i] = __float2bfloat16_rn(sp - __bfloat162float(h));
}

// ---------------------------------------------------------------------------
// Fused step kernel: pre = s'@W^T via 3x bf16 HMMA (hi*hi + hi*lo + lo*hi).
// 4 INDEPENDENT warpgroup pipelines (each: private k16 slice fill, private
// cp.async groups, private named barrier, 2x2 warps of 32x32 tiles), joined
// only at the final reduction + distributed epilogue.
__global__ void __launch_bounds__(THREADS, 1)
step_kernel(const float* __restrict__ inputs,
            const float* __restrict__ mask,
            const float* __restrict__ bias,
            const float* __restrict__ thr,
            const float* __restrict__ dec,
            const float* __restrict__ enc,
            float* __restrict__ out,
            int t) {
    extern __shared__ char smem[];
    const uint32_t sbase = s2u(smem);
    const int tid = threadIdx.x;
    const int wid = tid >> 5;
    const int lid = tid & 31;
    const int wg = wid >> 2;        // 0..3 : k16 slice owner
    const int wm = (wid >> 1) & 1;  // 32-row m tile
    const int wn = wid & 1;         // 32-col n tile
    const int n0 = blockIdx.x * BN;
    const int m0 = blockIdx.y * BM;

    const __nv_bfloat16* a_hi_r = g_a_hi + (size_t)(t & 1) * (BB * NN);
    const __nv_bfloat16* a_lo_r = g_a_lo + (size_t)(t & 1) * (BB * NN);
    __nv_bfloat16* a_hi_w = g_a_hi + (size_t)((t + 1) & 1) * (BB * NN);
    __nv_bfloat16* a_lo_w = g_a_lo + (size_t)((t + 1) & 1) * (BB * NN);

    // epilogue params into smem: [mask|bias|thr|dec0|dec1|enc0|enc1] x 64
    if (tid < 64) {
        float* pp = (float*)(smem + SMEM_PAR);
        int n = n0 + tid;
        pp[tid]       = mask[n];
        pp[64 + tid]  = bias[n];
        pp[128 + tid] = thr[n];
        pp[192 + tid] = dec[n];
        pp[256 + tid] = dec[NN + n];
        pp[320 + tid] = enc[n];
        pp[384 + tid] = enc[NN + n];
    }

    // ---- Per-wg fill: 128 threads fill this wg's 4 x 2KB slices ----
    // thread -> (row = wtid>>1, c = wtid&1); 4 cp16 per thread per chunk.
    const int wtid = tid & 127;
    const int frow = wtid >> 1;
    const int fc = wtid & 1;
    const uint32_t wgbase = sbase + SMEM_STAGE + wg * WG_B;
    const uint32_t fdst = frow * 32 + ((fc ^ ((frow >> 2) & 1)) << 4);
    const int fk = wg * 16 + fc * 8;   // k element offset within chunk
    const __nv_bfloat16* pAh = a_hi_r + (size_t)(m0 + frow) * NN + fk;
    const __nv_bfloat16* pAl = a_lo_r + (size_t)(m0 + frow) * NN + fk;
    const __nv_bfloat16* pWh = g_w_hi + (size_t)(n0 + frow) * NN + fk;
    const __nv_bfloat16* pWl = g_w_lo + (size_t)(n0 + frow) * NN + fk;
    uint32_t fstage = 0;

    auto fill = [&]() {
        const uint32_t sb = wgbase + fstage * STAGE_B;
        cp16(sb + 0 * WG_TILE_B + fdst, pAh);
        cp16(sb + 1 * WG_TILE_B + fdst, pAl);
        cp16(sb + 2 * WG_TILE_B + fdst, pWh);
        cp16(sb + 3 * WG_TILE_B + fdst, pWl);
        CP_COMMIT();
        pAh += BK; pAl += BK; pWh += BK; pWl += BK;
        fstage = (fstage + 1) & (NSTAGE - 1);
    };

    fill();
    fill();
    fill();

    // ---- ldsm offsets within this wg's slice (constants per thread) ----
    const int lrow8 = lid & 7;
    const int lgrp = lid >> 3;
    const int lc = lgrp >> 1;  // k8 half within this wg's k16
    uint32_t aoff[2], boff[2];
#pragma unroll
    for (int mi = 0; mi < 2; mi++) {
        int row = wm * 32 + mi * 16 + (lgrp & 1) * 8 + lrow8;
        aoff[mi] = row * 32 + ((lc ^ ((row >> 2) & 1)) << 4);
    }
#pragma unroll
    for (int ni = 0; ni < 2; ni++) {
        int row = wn * 32 + ni * 16 + (lgrp & 1) * 8 + lrow8;
        boff[ni] = row * 32 + ((lc ^ ((row >> 2) & 1)) << 4);
    }

    float acc[2][4][4];
#pragma unroll
    for (int i = 0; i < 2; i++)
#pragma unroll
        for (int q = 0; q < 4; q++)
#pragma unroll
            for (int r = 0; r < 4; r++) acc[i][q][r] = 0.0f;

    const int barid = wg + 1;

    // Preload hh fragments for chunk 0
    uint32_t ahb[2][2][4], bhb[2][2][4];
    CP_WAIT(2);
    WG_BAR(barid);
    {
        const uint32_t sb = wgbase;  // stage 0
#pragma unroll
        for (int mi = 0; mi < 2; mi++) ldsm4(ahb[0][mi], sb + 0 * WG_TILE_B + aoff[mi]);
#pragma unroll
        for (int ni = 0; ni < 2; ni++) ldsm4(bhb[0][ni], sb + 2 * WG_TILE_B + boff[ni]);
    }

#pragma unroll 2
    for (int c = 0; c < NIT; c++) {
        const int cur = c & 1;
        const int nxt = cur ^ 1;
        const uint32_t sb = wgbase + (c & (NSTAGE - 1)) * STAGE_B;
        const uint32_t sbn = wgbase + ((c + 1) & (NSTAGE - 1)) * STAGE_B;

        CP_WAIT(1);          // this wg's stages c and c+1 complete
        WG_BAR(barid);       // wg-local: publish fills, protect stage reuse

        // lo fragments of chunk c (hidden behind hh pass)
        uint32_t al[2][4], bl[2][4];
#pragma unroll
        for (int mi = 0; mi < 2; mi++) ldsm4(al[mi], sb + 1 * WG_TILE_B + aoff[mi]);
#pragma unroll
        for (int ni = 0; ni < 2; ni++) ldsm4(bl[ni], sb + 3 * WG_TILE_B + boff[ni]);

        // pass 1: hh (fragments already in registers)
#pragma unroll
        for (int mi = 0; mi < 2; mi++)
#pragma unroll
            for (int q = 0; q < 4; q++)
                mma16816(acc[mi][q], ahb[cur][mi], bhb[cur][q >> 1][q & 1],
                         bhb[cur][q >> 1][(q & 1) + 2]);

        if (c + 3 < NIT) fill();

        // prefetch hh fragments of chunk c+1 (hidden behind passes 2/3)
        if (c + 1 < NIT) {
#pragma unroll
            for (int mi = 0; mi < 2; mi++)
                ldsm4(ahb[nxt][mi], sbn + 0 * WG_TILE_B + aoff[mi]);
#pragma unroll
            for (int ni = 0; ni < 2; ni++)
                ldsm4(bhb[nxt][ni], sbn + 2 * WG_TILE_B + boff[ni]);
        }

        // pass 2: hi * lo
#pragma unroll
        for (int mi = 0; mi < 2; mi++)
#pragma unroll
            for (int q = 0; q < 4; q++)
                mma16816(acc[mi][q], ahb[cur][mi], bl[q >> 1][q & 1],
                         bl[q >> 1][(q & 1) + 2]);
        // pass 3: lo * hi
#pragma unroll
        for (int mi = 0; mi < 2; mi++)
#pragma unroll
            for (int q = 0; q < 4; q++)
                mma16816(acc[mi][q], al[mi], bhb[cur][q >> 1][q & 1],
                         bhb[cur][q >> 1][(q & 1) + 2]);
    }

    // ---- Join: dump all accumulators to smem in (wg, m, n) layout ----
    __syncthreads();
    float* red = (float*)(smem + SMEM_STAGE);   // 4 x 16KB, reuses stage area
    {
        const int mb = wm * 32 + (lid >> 2);
        const int nb = wn * 32 + ((lid & 3) << 1);
        float* rg = red + (wg << 12);           // wg * 4096
#pragma unroll
        for (int mi = 0; mi < 2; mi++)
#pragma unroll
            for (int q = 0; q < 4; q++)
#pragma unroll
                for (int rr = 0; rr < 4; rr++) {
                    int m = mb + mi * 16 + ((rr >> 1) << 3);
                    int n = nb + q * 8 + (rr & 1);
                    rg[m * 64 + n] = acc[mi][q][rr];
                }
    }
    __syncthreads();

    // ---- Distributed epilogue: thread -> (row em, 8 cols at en) ----
    const float* pp = (const float*)(smem + SMEM_PAR);
    const bool hasn = (t + 1 < TT);
    const int em = tid >> 3;          // 0..63
    const int en = (tid & 7) << 3;    // 0,8,...,56
    const int b = m0 + em;

    float pre[8];
    {
        const float* r0 = red + em * 64 + en;
        float4 u0 = *(const float4*)(r0);
        float4 u1 = *(const float4*)(r0 + 4);
#pragma unroll
        for (int g = 1; g < 4; g++) {
            const float* rg = r0 + (g << 12);
            float4 v0 = *(const float4*)(rg);
            float4 v1 = *(const float4*)(rg + 4);
            u0.x += v0.x; u0.y += v0.y; u0.z += v0.z; u0.w += v0.w;
            u1.x += v1.x; u1.y += v1.y; u1.z += v1.z; u1.w += v1.w;
        }
        pre[0] = u0.x; pre[1] = u0.y; pre[2] = u0.z; pre[3] = u0.w;
        pre[4] = u1.x; pre[5] = u1.y; pre[6] = u1.z; pre[7] = u1.w;
    }

    float x0 = 0.0f, x1 = 0.0f;
    if (hasn) {
        x0 = inputs[b * TT + t + 1];
        x1 = inputs[(BB + b) * TT + t + 1];
    }
    float p0 = 0.0f, p1 = 0.0f;
    __nv_bfloat16 hb[8], lb[8];
#pragma unroll
    for (int j = 0; j < 8; j++) {
        int nl = en + j;
        float mk = pp[nl];
        float z = SLOPE * (pre[j] - pp[128 + nl]);
        float sg = 1.0f / (1.0f + __expf(-z));
        float ns = mk * (pp[64 + nl] + sg);
        p0 = fmaf(ns, pp[192 + nl], p0);
        p1 = fmaf(ns, pp[256 + nl], p1);
        float sp = fmaf(mk, fmaf(x0, pp[320 + nl], x1 * pp[384 + nl]), ns);
        __nv_bfloat16 h = __float2bfloat16_rn(sp);
        hb[j] = h;
        lb[j] = __float2bfloat16_rn(sp - __bfloat162float(h));
    }
    if (hasn) {
        *(uint4*)(a_hi_w + (size_t)b * NN + n0 + en) = *(uint4*)hb;
        *(uint4*)(a_lo_w + (size_t)b * NN + n0 + en) = *(uint4*)lb;
    }

    // reduce decoder partials over the 8 lanes covering this row
    p0 += __shfl_xor_sync(0xffffffffu, p0, 1);
    p0 += __shfl_xor_sync(0xffffffffu, p0, 2);
    p0 += __shfl_xor_sync(0xffffffffu, p0, 4);
    p1 += __shfl_xor_sync(0xffffffffu, p1, 1);
    p1 += __shfl_xor_sync(0xffffffffu, p1, 2);
    p1 += __shfl_xor_sync(0xffffffffu, p1, 4);
    if ((lid & 7) == 0) {
        atomicAdd(&out[b * TT + t], p0);               // c = 0
        atomicAdd(&out[(BB + b) * TT + t], p1);        // c = 1
    }
}

// ---------------------------------------------------------------------------
extern "C" void kernel_launch(void* const* d_in, const int* in_sizes, int n_in,
                              void* d_out, int out_size) {
    const float* inputs = (const float*)d_in[0];  // [C,B,T]
    const float* state0 = (const float*)d_in[1];  // [B,N]
    const float* mask   = (const float*)d_in[2];  // [N]
    const float* enc    = (const float*)d_in[3];  // [C,N]
    const float* dec    = (const float*)d_in[4];  // [C,N]
    const float* W      = (const float*)d_in[5];  // [N,N]
    const float* bias   = (const float*)d_in[6];  // [N]
    const float* thr    = (const float*)d_in[7];  // [N]
    float* out = (float*)d_out;                   // [C,B,T]

    cudaFuncSetAttribute(step_kernel,
                         cudaFuncAttributeMaxDynamicSharedMemorySize, SMEM_TOTAL);

    zero_kernel<<<(CC * BB * TT + 255) / 256, 256>>>(out, CC * BB * TT);
    wconv_kernel<<<(NN * NN + 255) / 256, 256>>>(W);
    prep0_kernel<<<(BB * NN + 255) / 256, 256>>>(state0, inputs, mask, enc);

    dim3 grid(NN / BN, BB / BM);  // (32, 4) = 128 CTAs
    for (int t = 0; t < TT; t++) {
        step_kernel<<<grid, THREADS, SMEM_TOTAL>>>(inputs, mask, bias, thr,
                                                   dec, enc, out, t);
    }
}

// round 14
// speedup vs baseline: 1.1910x; 1.1910x over previous
#include <cuda_runtime.h>
#include <cuda_bf16.h>
#include <cstdint>

// Problem constants
#define NN 2048
#define BB 256
#define TT 256
#define CC 2
#define SLOPE 8.0f

// GEMM tiling: CTA 64x64, k-chunk 128, 512 threads (16 warps = 4 wg x (2x2))
#define BM 64
#define BN 64
#define BK 128
#define NIT (NN / BK)   // 16
#define THREADS 512

#define TILE_B (64 * 256)         // 16384 B: 64 rows x 128 bf16 (256B/row)
#define STAGE_B (4 * TILE_B)      // Ah, Al, Bh, Bl = 65536 B
#define NSTAGE 3
#define SMEM_PAR 0                // 7 x 64 floats = 1792 B
#define SMEM_STAGE 2048
#define SMEM_TOTAL (SMEM_STAGE + NSTAGE * STAGE_B)  // 198656 B

// Scratch, double-buffered in t-parity (allocation-free rule)
__device__ __align__(256) __nv_bfloat16 g_a_hi[2 * BB * NN];
__device__ __align__(256) __nv_bfloat16 g_a_lo[2 * BB * NN];
__device__ __align__(256) __nv_bfloat16 g_w_hi[NN * NN];
__device__ __align__(256) __nv_bfloat16 g_w_lo[NN * NN];

// ---------------------------------------------------------------------------
__device__ __forceinline__ uint32_t s2u(const void* p) {
    uint32_t a;
    asm("{ .reg .u64 t; cvta.to.shared.u64 t, %1; cvt.u32.u64 %0, t; }"
        : "=r"(a) : "l"(p));
    return a;
}

__device__ __forceinline__ void cp16(uint32_t dst, const void* src) {
    asm volatile("cp.async.cg.shared.global [%0], [%1], 16;\n"
                 :: "r"(dst), "l"(src));
}
#define CP_COMMIT() asm volatile("cp.async.commit_group;\n" ::: "memory")
#define CP_WAIT(n)  asm volatile("cp.async.wait_group %0;\n" :: "n"(n) : "memory")

__device__ __forceinline__ void ldsm4(uint32_t* r, uint32_t addr) {
    asm volatile("ldmatrix.sync.aligned.m8n8.x4.shared.b16 {%0,%1,%2,%3}, [%4];"
                 : "=r"(r[0]), "=r"(r[1]), "=r"(r[2]), "=r"(r[3]) : "r"(addr));
}

__device__ __forceinline__ void mma16816(float* c, const uint32_t* a,
                                         uint32_t b0, uint32_t b1) {
    asm volatile("mma.sync.aligned.m16n8k16.row.col.f32.bf16.bf16.f32 "
                 "{%0,%1,%2,%3}, {%4,%5,%6,%7}, {%8,%9}, {%0,%1,%2,%3};"
                 : "+f"(c[0]), "+f"(c[1]), "+f"(c[2]), "+f"(c[3])
                 : "r"(a[0]), "r"(a[1]), "r"(a[2]), "r"(a[3]),
                   "r"(b0), "r"(b1));
}

// ---------------------------------------------------------------------------
__global__ void zero_kernel(float* __restrict__ out, int n) {
    int i = blockIdx.x * blockDim.x + threadIdx.x;
    if (i < n) out[i] = 0.0f;
}

// W fp32 -> hi/lo bf16 (once per launch)
__global__ void wconv_kernel(const float* __restrict__ W) {
    int i = blockIdx.x * blockDim.x + threadIdx.x;
    if (i < NN * NN) {
        float w = W[i];
        __nv_bfloat16 h = __float2bfloat16_rn(w);
        g_w_hi[i] = h;
        g_w_lo[i] = __float2bfloat16_rn(w - __bfloat162float(h));
    }
}

// s'(0) = state0 + mask * ext(t=0), split hi/lo, into parity-0 buffer
__global__ void prep0_kernel(const float* __restrict__ state0,
                             const float* __restrict__ inputs,
                             const float* __restrict__ mask,
                             const float* __restrict__ enc) {
    int i = blockIdx.x * blockDim.x + threadIdx.x;
    int b = i >> 11;
    int n = i & (NN - 1);
    float x0 = inputs[b * TT];
    float x1 = inputs[(BB + b) * TT];
    float sp = state0[i] + mask[n] * (x0 * enc[n] + x1 * enc[NN + n]);
    __nv_bfloat16 h = __float2bfloat16_rn(sp);
    g_a_hi[i] = h;
    g_a_lo[i] = __float2bfloat16_rn(sp - __bfloat162float(h));
}

// ---------------------------------------------------------------------------
// Fused step kernel: pre = s'@W^T via 3x bf16 HMMA (hi*hi + hi*lo + lo*hi).
// 16 warps = 4 k-split warpgroups x (2x2) 32x32 warp tiles; BK=128 chunks
// (each wg owns a k32 slice = two k16 passes); static register-pipelined
// fragments; one __syncthreads per chunk (16 total).
__global__ void __launch_bounds__(THREADS, 1)
step_kernel(const float* __restrict__ inputs,
            const float* __restrict__ mask,
            const float* __restrict__ bias,
            const float* __restrict__ thr,
            const float* __restrict__ dec,
            const float* __restrict__ enc,
            float* __restrict__ out,
            int t) {
    extern __shared__ char smem[];
    const uint32_t sbase = s2u(smem);
    const int tid = threadIdx.x;
    const int wid = tid >> 5;
    const int lid = tid & 31;
    const int wg = wid >> 2;    // 0..3 : k32 slice within BK=128 chunk
    const int wq = wid & 3;
    const int wm = wq >> 1;     // 0..1 : 32-row m tile
    const int wn = wq & 1;      // 0..1 : 32-col n tile
    const int n0 = blockIdx.x * BN;
    const int m0 = blockIdx.y * BM;

    const __nv_bfloat16* a_hi_r = g_a_hi + (size_t)(t & 1) * (BB * NN);
    const __nv_bfloat16* a_lo_r = g_a_lo + (size_t)(t & 1) * (BB * NN);
    __nv_bfloat16* a_hi_w = g_a_hi + (size_t)((t + 1) & 1) * (BB * NN);
    __nv_bfloat16* a_lo_w = g_a_lo + (size_t)((t + 1) & 1) * (BB * NN);

    // epilogue params into smem: [mask|bias|thr|dec0|dec1|enc0|enc1] x 64
    if (tid < 64) {
        float* pp = (float*)(smem + SMEM_PAR);
        int n = n0 + tid;
        pp[tid]       = mask[n];
        pp[64 + tid]  = bias[n];
        pp[128 + tid] = thr[n];
        pp[192 + tid] = dec[n];
        pp[256 + tid] = dec[NN + n];
        pp[320 + tid] = enc[n];
        pp[384 + tid] = enc[NN + n];
    }

    // ---- Fill: 512 threads, 8 cp16 each (4 tiles x rows frow, frow+32) ----
    const int frow = tid >> 4;       // 0..31
    const int fch = tid & 15;        // 16B chunk within 256B row
    const uint32_t fdst = frow * 256 + ((fch ^ (frow & 7)) << 4);
    const __nv_bfloat16* pAh = a_hi_r + (size_t)(m0 + frow) * NN + fch * 8;
    const __nv_bfloat16* pAl = a_lo_r + (size_t)(m0 + frow) * NN + fch * 8;
    const __nv_bfloat16* pWh = g_w_hi + (size_t)(n0 + frow) * NN + fch * 8;
    const __nv_bfloat16* pWl = g_w_lo + (size_t)(n0 + frow) * NN + fch * 8;
    const size_t rstep = (size_t)32 * NN;   // +32 rows
    uint32_t fstage = 0;

    auto fill = [&]() {
        const uint32_t sb = sbase + SMEM_STAGE + fstage * STAGE_B;
        cp16(sb + 0 * TILE_B + fdst, pAh);
        cp16(sb + 0 * TILE_B + fdst + 8192, pAh + rstep);
        cp16(sb + 1 * TILE_B + fdst, pAl);
        cp16(sb + 1 * TILE_B + fdst + 8192, pAl + rstep);
        cp16(sb + 2 * TILE_B + fdst, pWh);
        cp16(sb + 2 * TILE_B + fdst + 8192, pWh + rstep);
        cp16(sb + 3 * TILE_B + fdst, pWl);
        cp16(sb + 3 * TILE_B + fdst + 8192, pWl + rstep);
        CP_COMMIT();
        pAh += BK; pAl += BK; pWh += BK; pWl += BK;
        fstage = (fstage == NSTAGE - 1) ? 0 : fstage + 1;
    };

    fill();
    fill();

    // ---- ldsm offsets: [ks][frag] constants per thread ----
    const int lrow8 = lid & 7;
    const int lgrp = lid >> 3;
    uint32_t aoff[2][2], boff[2][2];   // [ks][mi / ni]
#pragma unroll
    for (int ks = 0; ks < 2; ks++) {
        const int kch = wg * 4 + ks * 2 + (lgrp >> 1);
#pragma unroll
        for (int mi = 0; mi < 2; mi++) {
            int row = wm * 32 + mi * 16 + (lgrp & 1) * 8 + lrow8;
            aoff[ks][mi] = row * 256 + ((kch ^ (row & 7)) << 4);
        }
#pragma unroll
        for (int ni = 0; ni < 2; ni++) {
            int row = wn * 32 + ni * 16 + (lgrp & 1) * 8 + lrow8;
            boff[ks][ni] = row * 256 + ((kch ^ (row & 7)) << 4);
        }
    }

    float acc[2][4][4];
#pragma unroll
    for (int i = 0; i < 2; i++)
#pragma unroll
        for (int q = 0; q < 4; q++)
#pragma unroll
            for (int r = 0; r < 4; r++) acc[i][q][r] = 0.0f;

    // Fragment buffers: A = ks0 (and next chunk's ks0), B = ks1. Static roles.
    uint32_t ahA[2][4], bhA[2][4], ahB[2][4], bhB[2][4];

    // Preload hh fragments for chunk 0, ks0
    CP_WAIT(1);
    __syncthreads();
    {
        const uint32_t sb = sbase + SMEM_STAGE;  // stage 0
#pragma unroll
        for (int mi = 0; mi < 2; mi++) ldsm4(ahA[mi], sb + 0 * TILE_B + aoff[0][mi]);
#pragma unroll
        for (int ni = 0; ni < 2; ni++) ldsm4(bhA[ni], sb + 2 * TILE_B + boff[0][ni]);
    }

    uint32_t cstage = 0;
#pragma unroll 1
    for (int c = 0; c < NIT; c++) {
        const uint32_t sb = sbase + SMEM_STAGE + cstage * STAGE_B;
        cstage = (cstage == NSTAGE - 1) ? 0 : cstage + 1;
        const uint32_t sbn = sbase + SMEM_STAGE + cstage * STAGE_B;

        CP_WAIT(0);          // all issued fills done (incl. stage c+1)
        __syncthreads();     // publish fills; protect stage (c-1)%3 reuse

        uint32_t al[2][4], bl[2][4];
        // ks0 lo fragments
#pragma unroll
        for (int mi = 0; mi < 2; mi++) ldsm4(al[mi], sb + 1 * TILE_B + aoff[0][mi]);
#pragma unroll
        for (int ni = 0; ni < 2; ni++) ldsm4(bl[ni], sb + 3 * TILE_B + boff[0][ni]);

        // ks0 pass 1: hh
#pragma unroll
        for (int mi = 0; mi < 2; mi++)
#pragma unroll
            for (int q = 0; q < 4; q++)
                mma16816(acc[mi][q], ahA[mi], bhA[q >> 1][q & 1],
                         bhA[q >> 1][(q & 1) + 2]);

        if (c + 2 < NIT) fill();

        // ks1 hh fragments
#pragma unroll
        for (int mi = 0; mi < 2; mi++) ldsm4(ahB[mi], sb + 0 * TILE_B + aoff[1][mi]);
#pragma unroll
        for (int ni = 0; ni < 2; ni++) ldsm4(bhB[ni], sb + 2 * TILE_B + boff[1][ni]);

        // ks0 passes 2,3: hl, lh
#pragma unroll
        for (int mi = 0; mi < 2; mi++)
#pragma unroll
            for (int q = 0; q < 4; q++)
                mma16816(acc[mi][q], ahA[mi], bl[q >> 1][q & 1],
                         bl[q >> 1][(q & 1) + 2]);
#pragma unroll
        for (int mi = 0; mi < 2; mi++)
#pragma unroll
            for (int q = 0; q < 4; q++)
                mma16816(acc[mi][q], al[mi], bhA[q >> 1][q & 1],
                         bhA[q >> 1][(q & 1) + 2]);

        // ks1 lo fragments (reuse al/bl regs)
#pragma unroll
        for (int mi = 0; mi < 2; mi++) ldsm4(al[mi], sb + 1 * TILE_B + aoff[1][mi]);
#pragma unroll
        for (int ni = 0; ni < 2; ni++) ldsm4(bl[ni], sb + 3 * TILE_B + boff[1][ni]);

        // ks1 pass 1: hh
#pragma unroll
        for (int mi = 0; mi < 2; mi++)
#pragma unroll
            for (int q = 0; q < 4; q++)
                mma16816(acc[mi][q], ahB[mi], bhB[q >> 1][q & 1],
                         bhB[q >> 1][(q & 1) + 2]);

        // prefetch next chunk ks0 hh (stage c+1 complete per CP_WAIT(0))
        if (c + 1 < NIT) {
#pragma unroll
            for (int mi = 0; mi < 2; mi++)
                ldsm4(ahA[mi], sbn + 0 * TILE_B + aoff[0][mi]);
#pragma unroll
            for (int ni = 0; ni < 2; ni++)
                ldsm4(bhA[ni], sbn + 2 * TILE_B + boff[0][ni]);
        }

        // ks1 passes 2,3: hl, lh
#pragma unroll
        for (int mi = 0; mi < 2; mi++)
#pragma unroll
            for (int q = 0; q < 4; q++)
                mma16816(acc[mi][q], ahB[mi], bl[q >> 1][q & 1],
                         bl[q >> 1][(q & 1) + 2]);
#pragma unroll
        for (int mi = 0; mi < 2; mi++)
#pragma unroll
            for (int q = 0; q < 4; q++)
                mma16816(acc[mi][q], al[mi], bhB[q >> 1][q & 1],
                         bhB[q >> 1][(q & 1) + 2]);
    }

    // ---- Dump all accumulators to smem in (wg, m, n) layout ----
    __syncthreads();
    float* red = (float*)(smem + SMEM_STAGE);   // 4 x 16KB, reuses stage area
    {
        const int mb = wm * 32 + (lid >> 2);
        const int nb = wn * 32 + ((lid & 3) << 1);
        float* rg = red + (wg << 12);           // wg * 4096
#pragma unroll
        for (int mi = 0; mi < 2; mi++)
#pragma unroll
            for (int q = 0; q < 4; q++)
#pragma unroll
                for (int rr = 0; rr < 4; rr++) {
                    int m = mb + mi * 16 + ((rr >> 1) << 3);
                    int n = nb + q * 8 + (rr & 1);
                    rg[m * 64 + n] = acc[mi][q][rr];
                }
    }
    __syncthreads();

    // ---- Distributed epilogue: thread -> (row em, 8 cols at en) ----
    const float* pp = (const float*)(smem + SMEM_PAR);
    const bool hasn = (t + 1 < TT);
    const int em = tid >> 3;          // 0..63
    const int en = (tid & 7) << 3;    // 0,8,...,56
    const int b = m0 + em;

    float pre[8];
    {
        const float* r0 = red + em * 64 + en;
        float4 u0 = *(const float4*)(r0);
        float4 u1 = *(const float4*)(r0 + 4);
#pragma unroll
        for (int g = 1; g < 4; g++) {
            const float* rg = r0 + (g << 12);
            float4 v0 = *(const float4*)(rg);
            float4 v1 = *(const float4*)(rg + 4);
            u0.x += v0.x; u0.y += v0.y; u0.z += v0.z; u0.w += v0.w;
            u1.x += v1.x; u1.y += v1.y; u1.z += v1.z; u1.w += v1.w;
        }
        pre[0] = u0.x; pre[1] = u0.y; pre[2] = u0.z; pre[3] = u0.w;
        pre[4] = u1.x; pre[5] = u1.y; pre[6] = u1.z; pre[7] = u1.w;
    }

    float x0 = 0.0f, x1 = 0.0f;
    if (hasn) {
        x0 = inputs[b * TT + t + 1];
        x1 = inputs[(BB + b) * TT + t + 1];
    }
    float p0 = 0.0f, p1 = 0.0f;
    __nv_bfloat16 hb[8], lb[8];
#pragma unroll
    for (int j = 0; j < 8; j++) {
        int nl = en + j;
        float mk = pp[nl];
        float z = SLOPE * (pre[j] - pp[128 + nl]);
        float sg = 1.0f / (1.0f + __expf(-z));
        float ns = mk * (pp[64 + nl] + sg);
        p0 = fmaf(ns, pp[192 + nl], p0);
        p1 = fmaf(ns, pp[256 + nl], p1);
        float sp = fmaf(mk, fmaf(x0, pp[320 + nl], x1 * pp[384 + nl]), ns);
        __nv_bfloat16 h = __float2bfloat16_rn(sp);
        hb[j] = h;
        lb[j] = __float2bfloat16_rn(sp - __bfloat162float(h));
    }
    if (hasn) {
        *(uint4*)(a_hi_w + (size_t)b * NN + n0 + en) = *(uint4*)hb;
        *(uint4*)(a_lo_w + (size_t)b * NN + n0 + en) = *(uint4*)lb;
    }

    // reduce decoder partials over the 8 lanes covering this row
    p0 += __shfl_xor_sync(0xffffffffu, p0, 1);
    p0 += __shfl_xor_sync(0xffffffffu, p0, 2);
    p0 += __shfl_xor_sync(0xffffffffu, p0, 4);
    p1 += __shfl_xor_sync(0xffffffffu, p1, 1);
    p1 += __shfl_xor_sync(0xffffffffu, p1, 2);
    p1 += __shfl_xor_sync(0xffffffffu, p1, 4);
    if ((lid & 7) == 0) {
        atomicAdd(&out[b * TT + t], p0);               // c = 0
        atomicAdd(&out[(BB + b) * TT + t], p1);        // c = 1
    }
}

// ---------------------------------------------------------------------------
extern "C" void kernel_launch(void* const* d_in, const int* in_sizes, int n_in,
                              void* d_out, int out_size) {
    const float* inputs = (const float*)d_in[0];  // [C,B,T]
    const float* state0 = (const float*)d_in[1];  // [B,N]
    const float* mask   = (const float*)d_in[2];  // [N]
    const float* enc    = (const float*)d_in[3];  // [C,N]
    const float* dec    = (const float*)d_in[4];  // [C,N]
    const float* W      = (const float*)d_in[5];  // [N,N]
    const float* bias   = (const float*)d_in[6];  // [N]
    const float* thr    = (const float*)d_in[7];  // [N]
    float* out = (float*)d_out;                   // [C,B,T]

    cudaFuncSetAttribute(step_kernel,
                         cudaFuncAttributeMaxDynamicSharedMemorySize, SMEM_TOTAL);

    zero_kernel<<<(CC * BB * TT + 255) / 256, 256>>>(out, CC * BB * TT);
    wconv_kernel<<<(NN * NN + 255) / 256, 256>>>(W);
    prep0_kernel<<<(BB * NN + 255) / 256, 256>>>(state0, inputs, mask, enc);

    dim3 grid(NN / BN, BB / BM);  // (32, 4) = 128 CTAs
    for (int t = 0; t < TT; t++) {
        step_kernel<<<grid, THREADS, SMEM_TOTAL>>>(inputs, mask, bias, thr,
                                                   dec, enc, out, t);
    }
}